// round 3
// baseline (speedup 1.0000x reference)
#include <cuda_runtime.h>

typedef unsigned long long ull;

#define NB   64
#define NT   256
#define NIN  1024
#define NH   2048
#define NM   512
#define NHM  2560
#define NG   1536
#define NBLK 128
#define NTHR 256

// ---------------- device scratch (static, no allocation) ----------------
__device__ float g_xp[(size_t)NB * NT * NH];   // input projection [b*NT+t][h]
__device__ float g_h[2 * NB * NM];             // states h0 | h1
__device__ float g_linraw[NB * NH];            // pre-LN layer input
__device__ float g_ps1[NBLK * NB];             // per-block row sums
__device__ float g_ps2[NBLK * NB];             // per-block row sums of squares
__device__ float g_gp[(size_t)10 * NB * NG];   // G gemm split partials
__device__ unsigned g_cnt;                     // barrier counter (zero-init)
__device__ unsigned g_sense;                   // barrier sense    (zero-init)

// ---------------- f32x2 helpers ----------------
__device__ __forceinline__ void fma2(ull &d, ull a, ull b) {
    asm("fma.rn.f32x2 %0, %1, %2, %0;" : "+l"(d) : "l"(a), "l"(b));
}
__device__ __forceinline__ ull dup2(float x) {
    ull r; asm("mov.b64 %0, {%1, %1};" : "=l"(r) : "f"(x)); return r;
}
__device__ __forceinline__ float2 unp(ull v) {
    float2 r; asm("mov.b64 {%0, %1}, %2;" : "=f"(r.x), "=f"(r.y) : "l"(v)); return r;
}

// ---------------- sense-reversing grid barrier ----------------
__device__ __forceinline__ void gbar(unsigned &sense) {
    __syncthreads();
    if (threadIdx.x == 0) {
        sense ^= 1u;
        __threadfence();
        unsigned a = atomicAdd(&g_cnt, 1u);
        if (a == NBLK - 1u) {
            g_cnt = 0u;
            __threadfence();
            *(volatile unsigned*)&g_sense = sense;
        } else {
            while (*(volatile unsigned*)&g_sense != sense) { }
        }
        __threadfence();
    }
    __syncthreads();
}

// ---------------- 64x128 tile inner loop: 8 rows x 4 cols per thread ----------------
__device__ __forceinline__ void mm_inner(ull acc[4][4], const float* As, const float* Bs,
                                         int r0, int c0) {
#pragma unroll
    for (int k = 0; k < 32; k++) {
        const float* ar = As + k * 68 + r0;
        ull a0 = *(const ull*)(ar);
        ull a1 = *(const ull*)(ar + 2);
        ull a2 = *(const ull*)(ar + 4);
        ull a3 = *(const ull*)(ar + 6);
        float4 bf = *(const float4*)(Bs + k * 132 + c0);
        ull b0 = dup2(bf.x), b1 = dup2(bf.y), b2 = dup2(bf.z), b3 = dup2(bf.w);
        fma2(acc[0][0], a0, b0); fma2(acc[0][1], a0, b1); fma2(acc[0][2], a0, b2); fma2(acc[0][3], a0, b3);
        fma2(acc[1][0], a1, b0); fma2(acc[1][1], a1, b1); fma2(acc[1][2], a1, b2); fma2(acc[1][3], a1, b3);
        fma2(acc[2][0], a2, b0); fma2(acc[2][1], a2, b1); fma2(acc[2][2], a2, b2); fma2(acc[2][3], a2, b3);
        fma2(acc[3][0], a3, b0); fma2(acc[3][1], a3, b1); fma2(acc[3][2], a3, b2); fma2(acc[3][3], a3, b3);
    }
}

__global__ void __launch_bounds__(NTHR, 1)
ltc_all(const float* __restrict__ x,      const float* __restrict__ hidden,
        const float* __restrict__ W_in,   const float* __restrict__ b_in,
        const float* __restrict__ cell_W, const float* __restrict__ cell_b,
        const float* __restrict__ upd_W,  const float* __restrict__ upd_b,
        const float* __restrict__ rst_W,  const float* __restrict__ rst_b,
        const float* __restrict__ tau,
        const float* __restrict__ lc_W,   const float* __restrict__ lc_b,
        const float* __restrict__ sk_W,   const float* __restrict__ sk_b,
        const float* __restrict__ fb_W,   const float* __restrict__ fb_b,
        const float* __restrict__ ln_w,   const float* __restrict__ ln_b,
        const float* __restrict__ mn_w,   const float* __restrict__ mn_b,
        float* __restrict__ out)
{
    __shared__ float sAs[32 * 68];
    __shared__ float sBs[32 * 132];
    __shared__ float sMu[NB];
    __shared__ float sRi[NB];
    __shared__ float sR1[NTHR];
    __shared__ float sR2[NTHR];

    const int tid = threadIdx.x;
    const int bid = blockIdx.x;
    unsigned sense = *(volatile unsigned*)&g_sense;

    // ---- phase 0: load initial hidden states ----
    for (int i = bid * NTHR + tid; i < 2 * NB * NM; i += NBLK * NTHR)
        g_h[i] = hidden[i];
    gbar(sense);

    const int r0 = (tid >> 5) * 8;
    const int c0 = (tid & 31) * 4;

    // ---- phase 1: input projection xp = x . W_in^T ----
    for (int task = bid; task < 4096; task += NBLK) {
        int rowBase = (task >> 4) * 64;
        int colBase = (task & 15) * 128;
        ull acc[4][4];
#pragma unroll
        for (int i = 0; i < 4; i++)
#pragma unroll
            for (int j = 0; j < 4; j++) acc[i][j] = 0ull;
        for (int ku = 0; ku < NIN / 32; ku++) {
            int kc = ku * 32;
#pragma unroll
            for (int i = 0; i < 2; i++) {
                int id = tid + i * NTHR;
                int row = id >> 3, kq = id & 7;
                float4 v = *(const float4*)(x + (size_t)(rowBase + row) * NIN + kc + kq * 4);
                float* d = sAs + (kq * 4) * 68 + row;
                d[0] = v.x; d[68] = v.y; d[136] = v.z; d[204] = v.w;
            }
#pragma unroll
            for (int i = 0; i < 4; i++) {
                int id = tid + i * NTHR;
                int col = id >> 3, kq = id & 7;
                float4 v = *(const float4*)(W_in + (size_t)(colBase + col) * NIN + kc + kq * 4);
                float* d = sBs + (kq * 4) * 132 + col;
                d[0] = v.x; d[132] = v.y; d[264] = v.z; d[396] = v.w;
            }
            __syncthreads();
            mm_inner(acc, sAs, sBs, r0, c0);
            __syncthreads();
        }
#pragma unroll
        for (int rp = 0; rp < 4; rp++) {
            float2 p0 = unp(acc[rp][0]), p1 = unp(acc[rp][1]);
            float2 p2 = unp(acc[rp][2]), p3 = unp(acc[rp][3]);
            float4 lo = {p0.x, p1.x, p2.x, p3.x};
            float4 hi = {p0.y, p1.y, p2.y, p3.y};
            size_t rr = (size_t)(rowBase + r0 + 2 * rp);
            *(float4*)(g_xp + rr * NH + colBase + c0) = lo;
            *(float4*)(g_xp + (rr + 1) * NH + colBase + c0) = hi;
        }
    }
    gbar(sense);

    // ---- time loop ----
    for (int t = 0; t < NT; t++) {
        for (int l = 0; l < 2; l++) {
            const float* hsrc = (l == 0) ? (g_h + NB * NM) : g_h;  // L0: fb from h1; L1: skip/cross from updated h0

            // ======== phase P: projection + raw LN input + row-sum partials ========
            {
                int colBase = bid * 16;
                ull pacc[2] = {0ull, 0ull};
                const int pcol = tid & 15;
                const int pr0 = (tid >> 4) * 4;
                for (int ku = 0; ku < NM / 32; ku++) {
                    int kc = ku * 32;
#pragma unroll
                    for (int i = 0; i < 2; i++) {
                        int id = tid + i * NTHR;
                        int row = id >> 3, kq = id & 7;
                        float4 v = *(const float4*)(hsrc + (size_t)row * NM + kc + kq * 4);
                        float* d = sAs + (kq * 4) * 68 + row;
                        d[0] = v.x; d[68] = v.y; d[136] = v.z; d[204] = v.w;
                    }
                    if (tid < 128) {
                        int col = tid >> 3, kq = tid & 7;
                        size_t off = (size_t)(colBase + col) * NM + kc + kq * 4;
                        float4 v;
                        if (l == 0) {
                            v = *(const float4*)(fb_W + off);
                        } else {
                            v = *(const float4*)(sk_W + off);
                            float4 w = *(const float4*)(lc_W + off);
                            v.x += w.x; v.y += w.y; v.z += w.z; v.w += w.w;
                        }
                        float* d = sBs + (kq * 4) * 20 + col;
                        d[0] = v.x; d[20] = v.y; d[40] = v.z; d[60] = v.w;
                    }
                    __syncthreads();
#pragma unroll
                    for (int k = 0; k < 32; k++) {
                        const float* ar = sAs + k * 68 + pr0;
                        ull a0 = *(const ull*)ar;
                        ull a1 = *(const ull*)(ar + 2);
                        ull bb = dup2(sBs[k * 20 + pcol]);
                        fma2(pacc[0], a0, bb);
                        fma2(pacc[1], a1, bb);
                    }
                    __syncthreads();
                }
                // epilogue: LN-input values + deterministic row-sum partials
                int h = colBase + pcol;
                float2 q0 = unp(pacc[0]), q1 = unp(pacc[1]);
                float av[4] = {q0.x, q0.y, q1.x, q1.y};
                float s1[4], s2[4];
                float fbscale = (t == 0) ? 0.f : 0.1f;
#pragma unroll
                for (int j = 0; j < 4; j++) {
                    int b = pr0 + j;
                    float v;
                    if (l == 0)
                        v = g_xp[((size_t)b * NT + t) * NH + h] + b_in[h] + fbscale * (av[j] + fb_b[h]);
                    else
                        v = av[j] + sk_b[h] + lc_b[h];
                    g_linraw[(size_t)b * NH + h] = v;
                    s1[j] = v; s2[j] = v * v;
                }
#pragma unroll
                for (int off = 8; off > 0; off >>= 1) {
#pragma unroll
                    for (int j = 0; j < 4; j++) {
                        s1[j] += __shfl_xor_sync(0xffffffffu, s1[j], off);
                        s2[j] += __shfl_xor_sync(0xffffffffu, s2[j], off);
                    }
                }
                if ((tid & 15) == 0) {
#pragma unroll
                    for (int j = 0; j < 4; j++) {
                        g_ps1[bid * NB + pr0 + j] = s1[j];
                        g_ps2[bid * NB + pr0 + j] = s2[j];
                    }
                }
            }
            gbar(sense);

            // ======== phase G: stacked-gate GEMM, LN fused into A-load ========
            if (bid < 112) {
                if (tid < NB) {
                    float s1 = 0.f, s2 = 0.f;
                    for (int j = 0; j < NBLK; j++) {
                        s1 += g_ps1[j * NB + tid];
                        s2 += g_ps2[j * NB + tid];
                    }
                    float mu = s1 * (1.f / NH);
                    float var = s2 * (1.f / NH) - mu * mu;
                    sMu[tid] = mu;
                    sRi[tid] = rsqrtf(var + 1e-5f);
                }
                __syncthreads();
                int coltile, split;
                if (bid < 80) { coltile = bid / 10; split = bid - coltile * 10; }
                else          { int b2 = bid - 80; coltile = 8 + (b2 >> 3); split = b2 & 7; }
                int kbase = split * 256;
                int colBase = coltile * 128;
                const float* Wb; int ldb;
                if (coltile < 4)      { Wb = upd_W  + ((size_t)l * NM + colBase)          * NHM; ldb = NHM; }
                else if (coltile < 8) { Wb = rst_W  + ((size_t)l * NM + (colBase - 512))  * NHM; ldb = NHM; }
                else                  { Wb = cell_W + ((size_t)l * NM + (colBase - 1024)) * NH;  ldb = NH;  }
                const float* hself = g_h + l * NB * NM;
                const float* lnwl = ln_w + l * NH;
                const float* lnbl = ln_b + l * NH;
                ull acc[4][4];
#pragma unroll
                for (int i = 0; i < 4; i++)
#pragma unroll
                    for (int j = 0; j < 4; j++) acc[i][j] = 0ull;
                for (int ku = 0; ku < 8; ku++) {
                    int kc = kbase + ku * 32;
#pragma unroll
                    for (int i = 0; i < 2; i++) {
                        int id = tid + i * NTHR;
                        int row = id >> 3, kq = id & 7;
                        int kg = kc + kq * 4;
                        float4 v;
                        if (kg < NH) {
                            v = *(const float4*)(g_linraw + (size_t)row * NH + kg);
                            float4 w = *(const float4*)(lnwl + kg);
                            float4 bb = *(const float4*)(lnbl + kg);
                            float mu = sMu[row], ri = sRi[row];
                            v.x = (v.x - mu) * ri * w.x + bb.x;
                            v.y = (v.y - mu) * ri * w.y + bb.y;
                            v.z = (v.z - mu) * ri * w.z + bb.z;
                            v.w = (v.w - mu) * ri * w.w + bb.w;
                        } else {
                            v = *(const float4*)(hself + (size_t)row * NM + (kg - NH));
                        }
                        float* d = sAs + (kq * 4) * 68 + row;
                        d[0] = v.x; d[68] = v.y; d[136] = v.z; d[204] = v.w;
                    }
#pragma unroll
                    for (int i = 0; i < 4; i++) {
                        int id = tid + i * NTHR;
                        int col = id >> 3, kq = id & 7;
                        float4 v = *(const float4*)(Wb + (size_t)col * ldb + kc + kq * 4);
                        float* d = sBs + (kq * 4) * 132 + col;
                        d[0] = v.x; d[132] = v.y; d[264] = v.z; d[396] = v.w;
                    }
                    __syncthreads();
                    mm_inner(acc, sAs, sBs, r0, c0);
                    __syncthreads();
                }
#pragma unroll
                for (int rp = 0; rp < 4; rp++) {
                    float2 p0 = unp(acc[rp][0]), p1 = unp(acc[rp][1]);
                    float2 p2 = unp(acc[rp][2]), p3 = unp(acc[rp][3]);
                    float4 lo = {p0.x, p1.x, p2.x, p3.x};
                    float4 hi = {p0.y, p1.y, p2.y, p3.y};
                    int row = r0 + 2 * rp;
                    *(float4*)(g_gp + ((size_t)split * NB + row) * NG + colBase + c0) = lo;
                    *(float4*)(g_gp + ((size_t)split * NB + row + 1) * NG + colBase + c0) = hi;
                }
            }
            gbar(sense);

            // ======== phase C: split reduce + gates + mem-LN + write ========
            if (bid < NB) {
                int b = bid;
                float* hl = g_h + l * NB * NM;
                float hn[2];
#pragma unroll
                for (int j = 0; j < 2; j++) {
                    int m = tid + j * NTHR;
                    float su = 0.f, sr = 0.f, sc = 0.f;
#pragma unroll
                    for (int s = 0; s < 10; s++) {
                        size_t base = ((size_t)s * NB + b) * NG;
                        su += g_gp[base + m];
                        sr += g_gp[base + 512 + m];
                    }
#pragma unroll
                    for (int s = 0; s < 8; s++)
                        sc += g_gp[((size_t)s * NB + b) * NG + 1024 + m];
                    int lm = l * NM + m;
                    float u = 1.f / (1.f + expf(-(su + upd_b[lm])));
                    float r = 1.f / (1.f + expf(-(sr + rst_b[lm])));
                    float cand = tanhf(sc + cell_b[lm]);
                    float tv = tau[lm];
                    float sp = (tv > 20.f) ? tv : log1pf(expf(tv));
                    float tc = fminf(fmaxf(sp, 0.1f), 10.f);
                    float d = expf(-1.f / tc) * u;
                    float hp = hl[(size_t)b * NM + m];
                    hn[j] = d * (hp * r) + (1.f - d) * cand;
                }
                sR1[tid] = hn[0] + hn[1];
                sR2[tid] = hn[0] * hn[0] + hn[1] * hn[1];
                __syncthreads();
                for (int s = NTHR / 2; s > 0; s >>= 1) {
                    if (tid < s) { sR1[tid] += sR1[tid + s]; sR2[tid] += sR2[tid + s]; }
                    __syncthreads();
                }
                float mu = sR1[0] * (1.f / NM);
                float ri = rsqrtf(sR2[0] * (1.f / NM) - mu * mu + 1e-5f);
#pragma unroll
                for (int j = 0; j < 2; j++) {
                    int m = tid + j * NTHR;
                    int lm = l * NM + m;
                    float v = (hn[j] - mu) * ri * mn_w[lm] + mn_b[lm];
                    hl[(size_t)b * NM + m] = v;
                    if (l == 1) out[((size_t)b * NT + t) * NM + m] = v;
                }
            }
            gbar(sense);
        }
    }

    // ---- final hidden states hT = [L,B,M] appended after outs [B,T,M] ----
    for (int i = bid * NTHR + tid; i < 2 * NB * NM; i += NBLK * NTHR)
        out[(size_t)NB * NT * NM + i] = g_h[i];
}

extern "C" void kernel_launch(void* const* d_in, const int* in_sizes, int n_in,
                              void* d_out, int out_size)
{
    const float* x      = (const float*)d_in[0];
    const float* hidden = (const float*)d_in[1];
    const float* W_in   = (const float*)d_in[2];
    const float* b_in   = (const float*)d_in[3];
    const float* cell_W = (const float*)d_in[4];
    const float* cell_b = (const float*)d_in[5];
    const float* upd_W  = (const float*)d_in[6];
    const float* upd_b  = (const float*)d_in[7];
    const float* rst_W  = (const float*)d_in[8];
    const float* rst_b  = (const float*)d_in[9];
    const float* tau    = (const float*)d_in[10];
    const float* lc_W   = (const float*)d_in[11];
    const float* lc_b   = (const float*)d_in[12];
    const float* sk_W   = (const float*)d_in[13];
    const float* sk_b   = (const float*)d_in[14];
    const float* fb_W   = (const float*)d_in[15];
    const float* fb_b   = (const float*)d_in[16];
    const float* ln_w   = (const float*)d_in[17];
    const float* ln_b   = (const float*)d_in[18];
    const float* mn_w   = (const float*)d_in[19];
    const float* mn_b   = (const float*)d_in[20];
    float* out = (float*)d_out;

    ltc_all<<<NBLK, NTHR>>>(x, hidden, W_in, b_in, cell_W, cell_b,
                            upd_W, upd_b, rst_W, rst_b, tau,
                            lc_W, lc_b, sk_W, sk_b, fb_W, fb_b,
                            ln_w, ln_b, mn_w, mn_b, out);
}

// round 4
// speedup vs baseline: 1.0103x; 1.0103x over previous
#include <cuda_runtime.h>

typedef unsigned long long ull;

#define NB   64
#define NT   256
#define NIN  1024
#define NH   2048
#define NM   512
#define NHM  2560
#define NG   1536
#define NBLK 128
#define NTHR 256

// ---------------- device scratch (static, no allocation) ----------------
__device__ float g_xp[(size_t)NB * NT * NH];   // input projection [b*NT+t][h]
__device__ float g_h[2 * NB * NM];             // states h0 | h1
__device__ float g_linraw[NB * NH];            // pre-LN layer input
__device__ float g_ps1[NBLK * NB];             // per-block row sums
__device__ float g_ps2[NBLK * NB];             // per-block row sums of squares
__device__ float g_gp[(size_t)10 * NB * NG];   // G gemm split partials
__device__ unsigned g_cnt;                     // barrier counter (zero-init)
__device__ unsigned g_sense;                   // barrier sense    (zero-init)

// ---------------- f32x2 helpers ----------------
__device__ __forceinline__ void fma2(ull &d, ull a, ull b) {
    asm("fma.rn.f32x2 %0, %1, %2, %0;" : "+l"(d) : "l"(a), "l"(b));
}
__device__ __forceinline__ ull dup2(float x) {
    ull r; asm("mov.b64 %0, {%1, %1};" : "=l"(r) : "f"(x)); return r;
}
__device__ __forceinline__ float2 unp(ull v) {
    float2 r; asm("mov.b64 {%0, %1}, %2;" : "=f"(r.x), "=f"(r.y) : "l"(v)); return r;
}

// ---------------- sense-reversing grid barrier ----------------
__device__ __forceinline__ void gbar(unsigned &sense) {
    __syncthreads();
    if (threadIdx.x == 0) {
        sense ^= 1u;
        __threadfence();
        unsigned a = atomicAdd(&g_cnt, 1u);
        if (a == NBLK - 1u) {
            g_cnt = 0u;
            __threadfence();
            *(volatile unsigned*)&g_sense = sense;
        } else {
            while (*(volatile unsigned*)&g_sense != sense) { }
        }
        __threadfence();
    }
    __syncthreads();
}

// ---------------- 64x128 tile inner loop: 8 rows x 4 cols per thread ----------------
__device__ __forceinline__ void mm_inner(ull acc[4][4], const float* As, const float* Bs,
                                         int r0, int c0) {
#pragma unroll
    for (int k = 0; k < 32; k++) {
        const float* ar = As + k * 68 + r0;
        ull a0 = *(const ull*)(ar);
        ull a1 = *(const ull*)(ar + 2);
        ull a2 = *(const ull*)(ar + 4);
        ull a3 = *(const ull*)(ar + 6);
        float4 bf = *(const float4*)(Bs + k * 132 + c0);
        ull b0 = dup2(bf.x), b1 = dup2(bf.y), b2 = dup2(bf.z), b3 = dup2(bf.w);
        fma2(acc[0][0], a0, b0); fma2(acc[0][1], a0, b1); fma2(acc[0][2], a0, b2); fma2(acc[0][3], a0, b3);
        fma2(acc[1][0], a1, b0); fma2(acc[1][1], a1, b1); fma2(acc[1][2], a1, b2); fma2(acc[1][3], a1, b3);
        fma2(acc[2][0], a2, b0); fma2(acc[2][1], a2, b1); fma2(acc[2][2], a2, b2); fma2(acc[2][3], a2, b3);
        fma2(acc[3][0], a3, b0); fma2(acc[3][1], a3, b1); fma2(acc[3][2], a3, b2); fma2(acc[3][3], a3, b3);
    }
}

__global__ void __launch_bounds__(NTHR, 1)
ltc_all(const float* __restrict__ x,      const float* __restrict__ hidden,
        const float* __restrict__ W_in,   const float* __restrict__ b_in,
        const float* __restrict__ cell_W, const float* __restrict__ cell_b,
        const float* __restrict__ upd_W,  const float* __restrict__ upd_b,
        const float* __restrict__ rst_W,  const float* __restrict__ rst_b,
        const float* __restrict__ tau,
        const float* __restrict__ lc_W,   const float* __restrict__ lc_b,
        const float* __restrict__ sk_W,   const float* __restrict__ sk_b,
        const float* __restrict__ fb_W,   const float* __restrict__ fb_b,
        const float* __restrict__ ln_w,   const float* __restrict__ ln_b,
        const float* __restrict__ mn_w,   const float* __restrict__ mn_b,
        float* __restrict__ out)
{
    __shared__ float sAs[32 * 68];
    __shared__ float sBs[32 * 132];
    __shared__ float sMu[NB];
    __shared__ float sRi[NB];
    __shared__ float sR1[NTHR];
    __shared__ float sR2[NTHR];

    const int tid = threadIdx.x;
    const int bid = blockIdx.x;
    unsigned sense = *(volatile unsigned*)&g_sense;

    // ---- phase 0: load initial hidden states ----
    for (int i = bid * NTHR + tid; i < 2 * NB * NM; i += NBLK * NTHR)
        g_h[i] = hidden[i];
    gbar(sense);

    const int r0 = (tid >> 5) * 8;
    const int c0 = (tid & 31) * 4;

    // ---- phase 1: input projection xp = x . W_in^T ----
    for (int task = bid; task < 4096; task += NBLK) {
        int rowBase = (task >> 4) * 64;
        int colBase = (task & 15) * 128;
        ull acc[4][4];
#pragma unroll
        for (int i = 0; i < 4; i++)
#pragma unroll
            for (int j = 0; j < 4; j++) acc[i][j] = 0ull;
        for (int ku = 0; ku < NIN / 32; ku++) {
            int kc = ku * 32;
#pragma unroll
            for (int i = 0; i < 2; i++) {
                int id = tid + i * NTHR;
                int row = id >> 3, kq = id & 7;
                float4 v = *(const float4*)(x + (size_t)(rowBase + row) * NIN + kc + kq * 4);
                float* d = sAs + (kq * 4) * 68 + row;
                d[0] = v.x; d[68] = v.y; d[136] = v.z; d[204] = v.w;
            }
#pragma unroll
            for (int i = 0; i < 4; i++) {
                int id = tid + i * NTHR;
                int col = id >> 3, kq = id & 7;
                float4 v = *(const float4*)(W_in + (size_t)(colBase + col) * NIN + kc + kq * 4);
                float* d = sBs + (kq * 4) * 132 + col;
                d[0] = v.x; d[132] = v.y; d[264] = v.z; d[396] = v.w;
            }
            __syncthreads();
            mm_inner(acc, sAs, sBs, r0, c0);
            __syncthreads();
        }
#pragma unroll
        for (int rp = 0; rp < 4; rp++) {
            float2 p0 = unp(acc[rp][0]), p1 = unp(acc[rp][1]);
            float2 p2 = unp(acc[rp][2]), p3 = unp(acc[rp][3]);
            float4 lo = {p0.x, p1.x, p2.x, p3.x};
            float4 hi = {p0.y, p1.y, p2.y, p3.y};
            size_t rr = (size_t)(rowBase + r0 + 2 * rp);
            *(float4*)(g_xp + rr * NH + colBase + c0) = lo;
            *(float4*)(g_xp + (rr + 1) * NH + colBase + c0) = hi;
        }
    }
    gbar(sense);

    // ---- time loop ----
    for (int t = 0; t < NT; t++) {
        for (int l = 0; l < 2; l++) {
            const float* hsrc = (l == 0) ? (g_h + NB * NM) : g_h;  // L0: fb from h1; L1: skip/cross from updated h0

            // ======== phase P: projection + raw LN input + row-sum partials ========
            {
                int colBase = bid * 16;
                ull pacc[2] = {0ull, 0ull};
                const int pcol = tid & 15;
                const int pr0 = (tid >> 4) * 4;
                for (int ku = 0; ku < NM / 32; ku++) {
                    int kc = ku * 32;
#pragma unroll
                    for (int i = 0; i < 2; i++) {
                        int id = tid + i * NTHR;
                        int row = id >> 3, kq = id & 7;
                        float4 v = *(const float4*)(hsrc + (size_t)row * NM + kc + kq * 4);
                        float* d = sAs + (kq * 4) * 68 + row;
                        d[0] = v.x; d[68] = v.y; d[136] = v.z; d[204] = v.w;
                    }
                    if (tid < 128) {
                        int col = tid >> 3, kq = tid & 7;
                        size_t off = (size_t)(colBase + col) * NM + kc + kq * 4;
                        float4 v;
                        if (l == 0) {
                            v = *(const float4*)(fb_W + off);
                        } else {
                            v = *(const float4*)(sk_W + off);
                            float4 w = *(const float4*)(lc_W + off);
                            v.x += w.x; v.y += w.y; v.z += w.z; v.w += w.w;
                        }
                        float* d = sBs + (kq * 4) * 20 + col;
                        d[0] = v.x; d[20] = v.y; d[40] = v.z; d[60] = v.w;
                    }
                    __syncthreads();
#pragma unroll
                    for (int k = 0; k < 32; k++) {
                        const float* ar = sAs + k * 68 + pr0;
                        ull a0 = *(const ull*)ar;
                        ull a1 = *(const ull*)(ar + 2);
                        ull bb = dup2(sBs[k * 20 + pcol]);
                        fma2(pacc[0], a0, bb);
                        fma2(pacc[1], a1, bb);
                    }
                    __syncthreads();
                }
                // epilogue: LN-input values + deterministic row-sum partials
                int h = colBase + pcol;
                float2 q0 = unp(pacc[0]), q1 = unp(pacc[1]);
                float av[4] = {q0.x, q0.y, q1.x, q1.y};
                float s1[4], s2[4];
                float fbscale = (t == 0) ? 0.f : 0.1f;
#pragma unroll
                for (int j = 0; j < 4; j++) {
                    int b = pr0 + j;
                    float v;
                    if (l == 0)
                        v = g_xp[((size_t)b * NT + t) * NH + h] + b_in[h] + fbscale * (av[j] + fb_b[h]);
                    else
                        v = av[j] + sk_b[h] + lc_b[h];
                    g_linraw[(size_t)b * NH + h] = v;
                    s1[j] = v; s2[j] = v * v;
                }
#pragma unroll
                for (int off = 8; off > 0; off >>= 1) {
#pragma unroll
                    for (int j = 0; j < 4; j++) {
                        s1[j] += __shfl_xor_sync(0xffffffffu, s1[j], off);
                        s2[j] += __shfl_xor_sync(0xffffffffu, s2[j], off);
                    }
                }
                if ((tid & 15) == 0) {
#pragma unroll
                    for (int j = 0; j < 4; j++) {
                        g_ps1[bid * NB + pr0 + j] = s1[j];
                        g_ps2[bid * NB + pr0 + j] = s2[j];
                    }
                }
            }
            gbar(sense);

            // ======== phase G: stacked-gate GEMM, LN fused into A-load ========
            if (bid < 112) {
                if (tid < NB) {
                    float s1 = 0.f, s2 = 0.f;
                    for (int j = 0; j < NBLK; j++) {
                        s1 += g_ps1[j * NB + tid];
                        s2 += g_ps2[j * NB + tid];
                    }
                    float mu = s1 * (1.f / NH);
                    float var = s2 * (1.f / NH) - mu * mu;
                    sMu[tid] = mu;
                    sRi[tid] = rsqrtf(var + 1e-5f);
                }
                __syncthreads();
                int coltile, split;
                if (bid < 80) { coltile = bid / 10; split = bid - coltile * 10; }
                else          { int b2 = bid - 80; coltile = 8 + (b2 >> 3); split = b2 & 7; }
                int kbase = split * 256;
                int colBase = coltile * 128;
                const float* Wb; int ldb;
                if (coltile < 4)      { Wb = upd_W  + ((size_t)l * NM + colBase)          * NHM; ldb = NHM; }
                else if (coltile < 8) { Wb = rst_W  + ((size_t)l * NM + (colBase - 512))  * NHM; ldb = NHM; }
                else                  { Wb = cell_W + ((size_t)l * NM + (colBase - 1024)) * NH;  ldb = NH;  }
                const float* hself = g_h + l * NB * NM;
                const float* lnwl = ln_w + l * NH;
                const float* lnbl = ln_b + l * NH;
                ull acc[4][4];
#pragma unroll
                for (int i = 0; i < 4; i++)
#pragma unroll
                    for (int j = 0; j < 4; j++) acc[i][j] = 0ull;
                for (int ku = 0; ku < 8; ku++) {
                    int kc = kbase + ku * 32;
#pragma unroll
                    for (int i = 0; i < 2; i++) {
                        int id = tid + i * NTHR;
                        int row = id >> 3, kq = id & 7;
                        int kg = kc + kq * 4;
                        float4 v;
                        if (kg < NH) {
                            v = *(const float4*)(g_linraw + (size_t)row * NH + kg);
                            float4 w = *(const float4*)(lnwl + kg);
                            float4 bb = *(const float4*)(lnbl + kg);
                            float mu = sMu[row], ri = sRi[row];
                            v.x = (v.x - mu) * ri * w.x + bb.x;
                            v.y = (v.y - mu) * ri * w.y + bb.y;
                            v.z = (v.z - mu) * ri * w.z + bb.z;
                            v.w = (v.w - mu) * ri * w.w + bb.w;
                        } else {
                            v = *(const float4*)(hself + (size_t)row * NM + (kg - NH));
                        }
                        float* d = sAs + (kq * 4) * 68 + row;
                        d[0] = v.x; d[68] = v.y; d[136] = v.z; d[204] = v.w;
                    }
#pragma unroll
                    for (int i = 0; i < 4; i++) {
                        int id = tid + i * NTHR;
                        int col = id >> 3, kq = id & 7;
                        float4 v = *(const float4*)(Wb + (size_t)col * ldb + kc + kq * 4);
                        float* d = sBs + (kq * 4) * 132 + col;
                        d[0] = v.x; d[132] = v.y; d[264] = v.z; d[396] = v.w;
                    }
                    __syncthreads();
                    mm_inner(acc, sAs, sBs, r0, c0);
                    __syncthreads();
                }
#pragma unroll
                for (int rp = 0; rp < 4; rp++) {
                    float2 p0 = unp(acc[rp][0]), p1 = unp(acc[rp][1]);
                    float2 p2 = unp(acc[rp][2]), p3 = unp(acc[rp][3]);
                    float4 lo = {p0.x, p1.x, p2.x, p3.x};
                    float4 hi = {p0.y, p1.y, p2.y, p3.y};
                    int row = r0 + 2 * rp;
                    *(float4*)(g_gp + ((size_t)split * NB + row) * NG + colBase + c0) = lo;
                    *(float4*)(g_gp + ((size_t)split * NB + row + 1) * NG + colBase + c0) = hi;
                }
            }
            gbar(sense);

            // ======== phase C: split reduce + gates + mem-LN + write ========
            if (bid < NB) {
                int b = bid;
                float* hl = g_h + l * NB * NM;
                float hn[2];
#pragma unroll
                for (int j = 0; j < 2; j++) {
                    int m = tid + j * NTHR;
                    float su = 0.f, sr = 0.f, sc = 0.f;
#pragma unroll
                    for (int s = 0; s < 10; s++) {
                        size_t base = ((size_t)s * NB + b) * NG;
                        su += g_gp[base + m];
                        sr += g_gp[base + 512 + m];
                    }
#pragma unroll
                    for (int s = 0; s < 8; s++)
                        sc += g_gp[((size_t)s * NB + b) * NG + 1024 + m];
                    int lm = l * NM + m;
                    float u = 1.f / (1.f + expf(-(su + upd_b[lm])));
                    float r = 1.f / (1.f + expf(-(sr + rst_b[lm])));
                    float cand = tanhf(sc + cell_b[lm]);
                    float tv = tau[lm];
                    float sp = (tv > 20.f) ? tv : log1pf(expf(tv));
                    float tc = fminf(fmaxf(sp, 0.1f), 10.f);
                    float d = expf(-1.f / tc) * u;
                    float hp = hl[(size_t)b * NM + m];
                    hn[j] = d * (hp * r) + (1.f - d) * cand;
                }
                sR1[tid] = hn[0] + hn[1];
                sR2[tid] = hn[0] * hn[0] + hn[1] * hn[1];
                __syncthreads();
                for (int s = NTHR / 2; s > 0; s >>= 1) {
                    if (tid < s) { sR1[tid] += sR1[tid + s]; sR2[tid] += sR2[tid + s]; }
                    __syncthreads();
                }
                float mu = sR1[0] * (1.f / NM);
                float ri = rsqrtf(sR2[0] * (1.f / NM) - mu * mu + 1e-5f);
#pragma unroll
                for (int j = 0; j < 2; j++) {
                    int m = tid + j * NTHR;
                    int lm = l * NM + m;
                    float v = (hn[j] - mu) * ri * mn_w[lm] + mn_b[lm];
                    hl[(size_t)b * NM + m] = v;
                    if (l == 1) out[((size_t)b * NT + t) * NM + m] = v;
                }
            }
            gbar(sense);
        }
    }

    // ---- final hidden states hT = [L,B,M] appended after outs [B,T,M] ----
    for (int i = bid * NTHR + tid; i < 2 * NB * NM; i += NBLK * NTHR)
        out[(size_t)NB * NT * NM + i] = g_h[i];
}

extern "C" void kernel_launch(void* const* d_in, const int* in_sizes, int n_in,
                              void* d_out, int out_size)
{
    const float* x      = (const float*)d_in[0];
    const float* hidden = (const float*)d_in[1];
    const float* W_in   = (const float*)d_in[2];
    const float* b_in   = (const float*)d_in[3];
    const float* cell_W = (const float*)d_in[4];
    const float* cell_b = (const float*)d_in[5];
    const float* upd_W  = (const float*)d_in[6];
    const float* upd_b  = (const float*)d_in[7];
    const float* rst_W  = (const float*)d_in[8];
    const float* rst_b  = (const float*)d_in[9];
    const float* tau    = (const float*)d_in[10];
    const float* lc_W   = (const float*)d_in[11];
    const float* lc_b   = (const float*)d_in[12];
    const float* sk_W   = (const float*)d_in[13];
    const float* sk_b   = (const float*)d_in[14];
    const float* fb_W   = (const float*)d_in[15];
    const float* fb_b   = (const float*)d_in[16];
    const float* ln_w   = (const float*)d_in[17];
    const float* ln_b   = (const float*)d_in[18];
    const float* mn_w   = (const float*)d_in[19];
    const float* mn_b   = (const float*)d_in[20];
    float* out = (float*)d_out;

    ltc_all<<<NBLK, NTHR>>>(x, hidden, W_in, b_in, cell_W, cell_b,
                            upd_W, upd_b, rst_W, rst_b, tau,
                            lc_W, lc_b, sk_W, sk_b, fb_W, fb_b,
                            ln_w, ln_b, mn_w, mn_b, out);
}

// round 5
// speedup vs baseline: 1.3228x; 1.3093x over previous
#include <cuda_runtime.h>
#include <cstddef>

typedef unsigned long long ull;

#define NB 64
#define NT 256
#define NIN 1024
#define NH 2048
#define NM 512
#define NHM 2560
#define NG 1536
#define NBLK 128
#define NTHR 512

#define SA_STRIDE 96
#define SB_STRIDE 288
#define SA_BUF 3072
#define SB_BUF 9216
#define DYN_BYTES 98304

// ---------------- device scratch ----------------
__device__ float g_xp[(size_t)NB * NT * NH];
__device__ float g_h[2 * NB * NM];
__device__ float g_linraw[NB * NH];
__device__ float g_ps1[NBLK * NB];
__device__ float g_ps2[NBLK * NB];
__device__ float g_gp[(size_t)24 * NB * NG];
__device__ unsigned g_cnt;
__device__ unsigned g_sense;

// ---------------- f32x2 helpers ----------------
__device__ __forceinline__ void fma2(ull &d, ull a, ull b) {
    asm("fma.rn.f32x2 %0, %1, %2, %0;" : "+l"(d) : "l"(a), "l"(b));
}
__device__ __forceinline__ ull dup2(float x) {
    ull r; asm("mov.b64 %0, {%1, %1};" : "=l"(r) : "f"(x)); return r;
}
__device__ __forceinline__ float2 unp(ull v) {
    float2 r; asm("mov.b64 {%0, %1}, %2;" : "=f"(r.x), "=f"(r.y) : "l"(v)); return r;
}

// ---------------- grid barrier (acquire/release) ----------------
__device__ __forceinline__ void gbar(unsigned &sense) {
    __syncthreads();
    if (threadIdx.x == 0) {
        sense ^= 1u;
        __threadfence();
        unsigned a = atomicAdd(&g_cnt, 1u);
        if (a == NBLK - 1u) {
            g_cnt = 0u;
            asm volatile("st.global.release.gpu.u32 [%0], %1;"
                         :: "l"(&g_sense), "r"(sense) : "memory");
        } else {
            unsigned s;
            do {
                asm volatile("ld.global.acquire.gpu.u32 %0, [%1];"
                             : "=r"(s) : "l"(&g_sense) : "memory");
            } while (s != sense);
        }
    }
    __syncthreads();
}

// ---------------- 64x256 tile inner: 32 k-steps, 8 rows x 4 cols per thread --------
__device__ __forceinline__ void mm_k32(ull acc[4][4], const float* sAb, const float* sBb,
                                       int r0, int c0) {
#pragma unroll 8
    for (int k = 0; k < 32; k++) {
        int rot = k & 28;
        const float* ar = sAb + k * SA_STRIDE + rot + r0;
        ull a0 = *(const ull*)(ar);
        ull a1 = *(const ull*)(ar + 2);
        ull a2 = *(const ull*)(ar + 4);
        ull a3 = *(const ull*)(ar + 6);
        float4 bf = *(const float4*)(sBb + k * SB_STRIDE + rot + c0);
        ull b0 = dup2(bf.x), b1 = dup2(bf.y), b2 = dup2(bf.z), b3 = dup2(bf.w);
        fma2(acc[0][0], a0, b0); fma2(acc[0][1], a0, b1); fma2(acc[0][2], a0, b2); fma2(acc[0][3], a0, b3);
        fma2(acc[1][0], a1, b0); fma2(acc[1][1], a1, b1); fma2(acc[1][2], a1, b2); fma2(acc[1][3], a1, b3);
        fma2(acc[2][0], a2, b0); fma2(acc[2][1], a2, b1); fma2(acc[2][2], a2, b2); fma2(acc[2][3], a2, b3);
        fma2(acc[3][0], a3, b0); fma2(acc[3][1], a3, b1); fma2(acc[3][2], a3, b2); fma2(acc[3][3], a3, b3);
    }
}

#define STORE_AB(bsel) do { \
    float* dA = sA + (bsel) * SA_BUF + (akq * 4) * SA_STRIDE + akq * 4 + arow; \
    dA[0] = ra.x; dA[SA_STRIDE] = ra.y; dA[2 * SA_STRIDE] = ra.z; dA[3 * SA_STRIDE] = ra.w; \
    _Pragma("unroll") \
    for (int i2 = 0; i2 < 4; i2++) { \
        float* dB = sB + (bsel) * SB_BUF + (bkq[i2] * 4) * SB_STRIDE + bkq[i2] * 4 + bcol[i2]; \
        dB[0] = rb[i2].x; dB[SB_STRIDE] = rb[i2].y; \
        dB[2 * SB_STRIDE] = rb[i2].z; dB[3 * SB_STRIDE] = rb[i2].w; \
    } \
} while (0)

__global__ void __launch_bounds__(NTHR)
ltc_all(const float* __restrict__ x,      const float* __restrict__ hidden,
        const float* __restrict__ W_in,   const float* __restrict__ b_in,
        const float* __restrict__ cell_W, const float* __restrict__ cell_b,
        const float* __restrict__ upd_W,  const float* __restrict__ upd_b,
        const float* __restrict__ rst_W,  const float* __restrict__ rst_b,
        const float* __restrict__ tau,
        const float* __restrict__ lc_W,   const float* __restrict__ lc_b,
        const float* __restrict__ sk_W,   const float* __restrict__ sk_b,
        const float* __restrict__ fb_W,   const float* __restrict__ fb_b,
        const float* __restrict__ ln_w,   const float* __restrict__ ln_b,
        const float* __restrict__ mn_w,   const float* __restrict__ mn_b,
        float* __restrict__ out)
{
    extern __shared__ float dyn[];
    float* sA = dyn;                    // 2 x 3072 floats
    float* sB = dyn + 2 * SA_BUF;       // 2 x 9216 floats
    __shared__ float sMu[NB], sRi[NB];
    __shared__ float sR1[NTHR], sR2[NTHR];
    __shared__ float sCmb[NB * 16];

    const int tid = threadIdx.x;
    const int bid = blockIdx.x;
    unsigned sense;
    asm volatile("ld.global.acquire.gpu.u32 %0, [%1];" : "=r"(sense) : "l"(&g_sense) : "memory");

    // ---- init hidden states ----
    for (int i = bid * NTHR + tid; i < 2 * NB * NM; i += NBLK * NTHR)
        g_h[i] = hidden[i];
    gbar(sense);

    const int arow = tid >> 3, akq = tid & 7;
    int bcol[4], bkq[4];
#pragma unroll
    for (int i = 0; i < 4; i++) { int id = tid + i * NTHR; bcol[i] = id >> 3; bkq[i] = id & 7; }
    const int r0 = (tid >> 6) * 8;
    const int c0 = (tid & 63) * 4;

    // ---- input projection: xp = x . W_in^T  (2048 tasks of 64x256, dbuf pipeline) ----
    for (int p = 0; p < 16; p++) {
        int task = bid + p * NBLK;
        int rowBase = (task >> 3) * 64, colBase = (task & 7) * 256;
        ull acc[4][4];
#pragma unroll
        for (int i = 0; i < 4; i++)
#pragma unroll
            for (int j = 0; j < 4; j++) acc[i][j] = 0ull;
        float4 ra, rb[4];
        {
            ra = *(const float4*)(x + (size_t)(rowBase + arow) * NIN + akq * 4);
#pragma unroll
            for (int i = 0; i < 4; i++)
                rb[i] = *(const float4*)(W_in + (size_t)(colBase + bcol[i]) * NIN + bkq[i] * 4);
        }
        STORE_AB(0);
        __syncthreads();
        for (int ku = 0; ku < 32; ku++) {
            if (ku + 1 < 32) {
                int kc = (ku + 1) * 32;
                ra = *(const float4*)(x + (size_t)(rowBase + arow) * NIN + kc + akq * 4);
#pragma unroll
                for (int i = 0; i < 4; i++)
                    rb[i] = *(const float4*)(W_in + (size_t)(colBase + bcol[i]) * NIN + kc + bkq[i] * 4);
            }
            mm_k32(acc, sA + (ku & 1) * SA_BUF, sB + (ku & 1) * SB_BUF, r0, c0);
            if (ku + 1 < 32) STORE_AB((ku + 1) & 1);
            __syncthreads();
        }
#pragma unroll
        for (int rp = 0; rp < 4; rp++) {
            float2 p0 = unp(acc[rp][0]), p1 = unp(acc[rp][1]);
            float2 p2 = unp(acc[rp][2]), p3 = unp(acc[rp][3]);
            float4 lo = {p0.x, p1.x, p2.x, p3.x};
            float4 hi = {p0.y, p1.y, p2.y, p3.y};
            size_t rr = (size_t)rowBase + r0 + 2 * rp;
            *(float4*)(g_xp + rr * NH + colBase + c0) = lo;
            *(float4*)(g_xp + (rr + 1) * NH + colBase + c0) = hi;
        }
    }
    gbar(sense);

    // ---- time loop ----
    for (int t = 0; t < NT; t++) {
        for (int l = 0; l < 2; l++) {
            const float* hsrc = (l == 0) ? (g_h + NB * NM) : g_h;

            // ======== phase P: projection (K split in 2 warp-halves) ========
            {
                int colBase = bid * 16;
                float* sBp = dyn;                              // 512 x 17 = 8704 floats
                const int half = tid >> 8;
                float* sApH = dyn + 8704 + half * 2176;        // per-half 32 x 68
#pragma unroll
                for (int i = 0; i < 4; i++) {
                    int id = tid + i * NTHR;
                    int c = id >> 7, kq = id & 127;
                    size_t off = (size_t)(colBase + c) * NM + kq * 4;
                    float4 v;
                    if (l == 0) {
                        v = *(const float4*)(fb_W + off);
                    } else {
                        v = *(const float4*)(sk_W + off);
                        float4 w = *(const float4*)(lc_W + off);
                        v.x += w.x; v.y += w.y; v.z += w.z; v.w += w.w;
                    }
                    float* d = sBp + (kq * 4) * 17 + c;
                    d[0] = v.x; d[17] = v.y; d[34] = v.z; d[51] = v.w;
                }
                ull pacc[2] = {0ull, 0ull};
                const int pcol = tid & 15;
                const int pr0 = ((tid >> 4) & 15) * 4;
                const int hid = tid & 255;
                __syncthreads();
                for (int ku = 0; ku < 8; ku++) {
                    int kA = half * 256 + ku * 32;
#pragma unroll
                    for (int i = 0; i < 2; i++) {
                        int id = hid + i * 256;
                        int row = id >> 3, kq = id & 7;
                        float4 v = *(const float4*)(hsrc + (size_t)row * NM + kA + kq * 4);
                        float* d = sApH + (kq * 4) * 68 + row;
                        d[0] = v.x; d[68] = v.y; d[136] = v.z; d[204] = v.w;
                    }
                    __syncthreads();
#pragma unroll 8
                    for (int k = 0; k < 32; k++) {
                        const float* ar = sApH + k * 68 + pr0;
                        ull a0 = *(const ull*)ar;
                        ull a1 = *(const ull*)(ar + 2);
                        ull bb = dup2(sBp[(kA + k) * 17 + pcol]);
                        fma2(pacc[0], a0, bb);
                        fma2(pacc[1], a1, bb);
                    }
                    __syncthreads();
                }
                float2 q0 = unp(pacc[0]), q1 = unp(pacc[1]);
                float av[4] = {q0.x, q0.y, q1.x, q1.y};
                if (half == 1) {
#pragma unroll
                    for (int j = 0; j < 4; j++)
                        sCmb[(pr0 + j) * 16 + pcol] = av[j];
                }
                __syncthreads();
                if (half == 0) {
                    int h = colBase + pcol;
                    float s1[4], s2[4];
                    float fbscale = (t == 0) ? 0.f : 0.1f;
#pragma unroll
                    for (int j = 0; j < 4; j++) {
                        int b = pr0 + j;
                        float v = av[j] + sCmb[b * 16 + pcol];
                        if (l == 0)
                            v = g_xp[((size_t)b * NT + t) * NH + h] + b_in[h] + fbscale * (v + fb_b[h]);
                        else
                            v = v + sk_b[h] + lc_b[h];
                        g_linraw[(size_t)b * NH + h] = v;
                        s1[j] = v; s2[j] = v * v;
                    }
#pragma unroll
                    for (int off = 8; off > 0; off >>= 1) {
#pragma unroll
                        for (int j = 0; j < 4; j++) {
                            s1[j] += __shfl_xor_sync(0xffffffffu, s1[j], off);
                            s2[j] += __shfl_xor_sync(0xffffffffu, s2[j], off);
                        }
                    }
                    if (pcol == 0) {
#pragma unroll
                        for (int j = 0; j < 4; j++) {
                            g_ps1[bid * NB + pr0 + j] = s1[j];
                            g_ps2[bid * NB + pr0 + j] = s2[j];
                        }
                    }
                }
            }
            gbar(sense);

            // ======== phase G: stacked-gate GEMM, LN fused in A-load ========
            {
                if (tid < NB) {
                    float s1 = 0.f, s2 = 0.f;
                    for (int j = 0; j < NBLK; j++) {
                        s1 += g_ps1[j * NB + tid];
                        s2 += g_ps2[j * NB + tid];
                    }
                    float mu = s1 * (1.f / NH);
                    sMu[tid] = mu;
                    sRi[tid] = rsqrtf(s2 * (1.f / NH) - mu * mu + 1e-5f);
                }
                __syncthreads();
                int split, nk, kb, outCol, ldb;
                const float* Wb;
                if (bid < 96) {
                    int coltile = bid / 24; split = bid % 24;
                    nk = (split < 8) ? 4 : 3;
                    kb = ((split < 8) ? 4 * split : 32 + 3 * (split - 8)) * 32;
                    int colBase = coltile * 256;
                    if (colBase < 512) Wb = upd_W + ((size_t)l * NM + colBase) * NHM;
                    else               Wb = rst_W + ((size_t)l * NM + colBase - 512) * NHM;
                    ldb = NHM; outCol = colBase;
                } else {
                    int b2 = bid - 96;
                    int coltile = b2 >> 4; split = b2 & 15;
                    nk = 4; kb = split * 128;
                    int colBase = coltile * 256;
                    Wb = cell_W + ((size_t)l * NM + colBase) * NH;
                    ldb = NH; outCol = 1024 + colBase;
                }
                const float* hself = g_h + l * NB * NM;
                const float* lnwl = ln_w + l * NH;
                const float* lnbl = ln_b + l * NH;
                ull acc[4][4];
#pragma unroll
                for (int i = 0; i < 4; i++)
#pragma unroll
                    for (int j = 0; j < 4; j++) acc[i][j] = 0ull;
                float4 ra, rb[4];
#define G_LOAD(KU) do { \
    int kc = kb + (KU) * 32; \
    int kg = kc + akq * 4; \
    if (kg < NH) { \
        ra = *(const float4*)(g_linraw + (size_t)arow * NH + kg); \
        float4 w = *(const float4*)(lnwl + kg); \
        float4 b2v = *(const float4*)(lnbl + kg); \
        float mu = sMu[arow], ri = sRi[arow]; \
        ra.x = (ra.x - mu) * ri * w.x + b2v.x; \
        ra.y = (ra.y - mu) * ri * w.y + b2v.y; \
        ra.z = (ra.z - mu) * ri * w.z + b2v.z; \
        ra.w = (ra.w - mu) * ri * w.w + b2v.w; \
    } else { \
        ra = *(const float4*)(hself + (size_t)arow * NM + (kg - NH)); \
    } \
    _Pragma("unroll") \
    for (int i2 = 0; i2 < 4; i2++) \
        rb[i2] = *(const float4*)(Wb + (size_t)bcol[i2] * ldb + kc + bkq[i2] * 4); \
} while (0)
                G_LOAD(0);
                STORE_AB(0);
                __syncthreads();
                for (int ku = 0; ku < nk; ku++) {
                    if (ku + 1 < nk) G_LOAD(ku + 1);
                    mm_k32(acc, sA + (ku & 1) * SA_BUF, sB + (ku & 1) * SB_BUF, r0, c0);
                    if (ku + 1 < nk) STORE_AB((ku + 1) & 1);
                    __syncthreads();
                }
#pragma unroll
                for (int rp = 0; rp < 4; rp++) {
                    float2 p0 = unp(acc[rp][0]), p1 = unp(acc[rp][1]);
                    float2 p2 = unp(acc[rp][2]), p3 = unp(acc[rp][3]);
                    float4 lo = {p0.x, p1.x, p2.x, p3.x};
                    float4 hi = {p0.y, p1.y, p2.y, p3.y};
                    int row = r0 + 2 * rp;
                    *(float4*)(g_gp + ((size_t)split * NB + row) * NG + outCol + c0) = lo;
                    *(float4*)(g_gp + ((size_t)split * NB + row + 1) * NG + outCol + c0) = hi;
                }
            }
            gbar(sense);

            // ======== phase C: split reduce + gates + mem-LN + write ========
            if (bid < NB) {
                int b = bid, m = tid;
                float* hl = g_h + l * NB * NM;
                float su = 0.f, sr = 0.f, sc = 0.f;
#pragma unroll
                for (int s = 0; s < 24; s++) {
                    size_t base = ((size_t)s * NB + b) * NG;
                    su += g_gp[base + m];
                    sr += g_gp[base + 512 + m];
                }
#pragma unroll
                for (int s = 0; s < 16; s++)
                    sc += g_gp[((size_t)s * NB + b) * NG + 1024 + m];
                int lm = l * NM + m;
                float u = 1.f / (1.f + expf(-(su + upd_b[lm])));
                float r = 1.f / (1.f + expf(-(sr + rst_b[lm])));
                float cand = tanhf(sc + cell_b[lm]);
                float tv = tau[lm];
                float sp = (tv > 20.f) ? tv : log1pf(expf(tv));
                float tc = fminf(fmaxf(sp, 0.1f), 10.f);
                float d = expf(-1.f / tc) * u;
                float hp = hl[(size_t)b * NM + m];
                float hn = d * (hp * r) + (1.f - d) * cand;
                sR1[tid] = hn;
                sR2[tid] = hn * hn;
                __syncthreads();
                for (int s = NTHR / 2; s > 0; s >>= 1) {
                    if (tid < s) { sR1[tid] += sR1[tid + s]; sR2[tid] += sR2[tid + s]; }
                    __syncthreads();
                }
                float mu = sR1[0] * (1.f / NM);
                float ri = rsqrtf(sR2[0] * (1.f / NM) - mu * mu + 1e-5f);
                float v = (hn - mu) * ri * mn_w[lm] + mn_b[lm];
                hl[(size_t)b * NM + m] = v;
                if (l == 1) out[((size_t)b * NT + t) * NM + m] = v;
            }
            gbar(sense);
        }
    }

    // ---- final hidden states hT appended after outs [B,T,M] ----
    for (int i = bid * NTHR + tid; i < 2 * NB * NM; i += NBLK * NTHR)
        out[(size_t)NB * NT * NM + i] = g_h[i];
}

extern "C" void kernel_launch(void* const* d_in, const int* in_sizes, int n_in,
                              void* d_out, int out_size)
{
    const float* x      = (const float*)d_in[0];
    const float* hidden = (const float*)d_in[1];
    const float* W_in   = (const float*)d_in[2];
    const float* b_in   = (const float*)d_in[3];
    const float* cell_W = (const float*)d_in[4];
    const float* cell_b = (const float*)d_in[5];
    const float* upd_W  = (const float*)d_in[6];
    const float* upd_b  = (const float*)d_in[7];
    const float* rst_W  = (const float*)d_in[8];
    const float* rst_b  = (const float*)d_in[9];
    const float* tau    = (const float*)d_in[10];
    const float* lc_W   = (const float*)d_in[11];
    const float* lc_b   = (const float*)d_in[12];
    const float* sk_W   = (const float*)d_in[13];
    const float* sk_b   = (const float*)d_in[14];
    const float* fb_W   = (const float*)d_in[15];
    const float* fb_b   = (const float*)d_in[16];
    const float* ln_w   = (const float*)d_in[17];
    const float* ln_b   = (const float*)d_in[18];
    const float* mn_w   = (const float*)d_in[19];
    const float* mn_b   = (const float*)d_in[20];
    float* out = (float*)d_out;

    cudaFuncSetAttribute(ltc_all, cudaFuncAttributeMaxDynamicSharedMemorySize, DYN_BYTES);
    ltc_all<<<NBLK, NTHR, DYN_BYTES>>>(x, hidden, W_in, b_in, cell_W, cell_b,
                                       upd_W, upd_b, rst_W, rst_b, tau,
                                       lc_W, lc_b, sk_W, sk_b, fb_W, fb_b,
                                       ln_w, ln_b, mn_w, mn_b, out);
}

// round 6
// speedup vs baseline: 1.7677x; 1.3364x over previous
#include <cuda_runtime.h>
#include <cstddef>

typedef unsigned long long ull;

#define NB 64
#define NT 256
#define NIN 1024
#define NH 2048
#define NM 512
#define NHM 2560
#define NG 1536
#define NBLK 128
#define NTHR 512

#define SA_STRIDE 96
#define SB_STRIDE 288
#define SA_BUF 3072
#define SB_BUF 9216
#define DYN_BYTES 98304

// ---------------- device scratch ----------------
__device__ float g_xp[(size_t)NB * NT * NH];
__device__ float g_h[2 * NB * NM];
__device__ float g_linraw[NB * NH];
__device__ float g_pp[(size_t)16 * NB * NH];   // P gemm split partials
__device__ float g_ps1[NBLK];                  // per (row,half) stat partials
__device__ float g_ps2[NBLK];
__device__ float g_gp[(size_t)24 * NB * NG];   // G gemm split partials
__device__ float g_cWc[(size_t)NH * NM];       // sk_W + lc_W
__device__ float g_cbc[NH];                    // sk_b + lc_b
__device__ float g_dcoef[2 * NM];              // exp(-1/clip(softplus(tau)))
__device__ unsigned g_cnt;
__device__ unsigned g_sense;

// ---------------- f32x2 helpers ----------------
__device__ __forceinline__ void fma2(ull &d, ull a, ull b) {
    asm("fma.rn.f32x2 %0, %1, %2, %0;" : "+l"(d) : "l"(a), "l"(b));
}
__device__ __forceinline__ ull dup2(float x) {
    ull r; asm("mov.b64 %0, {%1, %1};" : "=l"(r) : "f"(x)); return r;
}
__device__ __forceinline__ float2 unp(ull v) {
    float2 r; asm("mov.b64 {%0, %1}, %2;" : "=f"(r.x), "=f"(r.y) : "l"(v)); return r;
}

// ---------------- grid barrier ----------------
__device__ __forceinline__ void gbar(unsigned &sense) {
    __syncthreads();
    if (threadIdx.x == 0) {
        sense ^= 1u;
        __threadfence();
        unsigned a = atomicAdd(&g_cnt, 1u);
        if (a == NBLK - 1u) {
            g_cnt = 0u;
            asm volatile("st.global.release.gpu.u32 [%0], %1;"
                         :: "l"(&g_sense), "r"(sense) : "memory");
        } else {
            unsigned s;
            do {
                asm volatile("ld.global.acquire.gpu.u32 %0, [%1];"
                             : "=r"(s) : "l"(&g_sense) : "memory");
            } while (s != sense);
        }
    }
    __syncthreads();
}

// ---------------- 64x256 tile inner: 32 k-steps, 8 rows x 4 cols per thread --------
__device__ __forceinline__ void mm_k32(ull acc[4][4], const float* sAb, const float* sBb,
                                       int r0, int c0) {
#pragma unroll 8
    for (int k = 0; k < 32; k++) {
        int rot = k & 28;
        const float* ar = sAb + k * SA_STRIDE + rot + r0;
        ull a0 = *(const ull*)(ar);
        ull a1 = *(const ull*)(ar + 2);
        ull a2 = *(const ull*)(ar + 4);
        ull a3 = *(const ull*)(ar + 6);
        float4 bf = *(const float4*)(sBb + k * SB_STRIDE + rot + c0);
        ull b0 = dup2(bf.x), b1 = dup2(bf.y), b2 = dup2(bf.z), b3 = dup2(bf.w);
        fma2(acc[0][0], a0, b0); fma2(acc[0][1], a0, b1); fma2(acc[0][2], a0, b2); fma2(acc[0][3], a0, b3);
        fma2(acc[1][0], a1, b0); fma2(acc[1][1], a1, b1); fma2(acc[1][2], a1, b2); fma2(acc[1][3], a1, b3);
        fma2(acc[2][0], a2, b0); fma2(acc[2][1], a2, b1); fma2(acc[2][2], a2, b2); fma2(acc[2][3], a2, b3);
        fma2(acc[3][0], a3, b0); fma2(acc[3][1], a3, b1); fma2(acc[3][2], a3, b2); fma2(acc[3][3], a3, b3);
    }
}

#define STORE_AB(bsel) do { \
    float* dA = sA + (bsel) * SA_BUF + (akq * 4) * SA_STRIDE + akq * 4 + arow; \
    dA[0] = ra.x; dA[SA_STRIDE] = ra.y; dA[2 * SA_STRIDE] = ra.z; dA[3 * SA_STRIDE] = ra.w; \
    _Pragma("unroll") \
    for (int i2 = 0; i2 < 4; i2++) { \
        float* dB = sB + (bsel) * SB_BUF + (bkq[i2] * 4) * SB_STRIDE + bkq[i2] * 4 + bcol[i2]; \
        dB[0] = rb[i2].x; dB[SB_STRIDE] = rb[i2].y; \
        dB[2 * SB_STRIDE] = rb[i2].z; dB[3 * SB_STRIDE] = rb[i2].w; \
    } \
} while (0)

__global__ void __launch_bounds__(NTHR)
ltc_all(const float* __restrict__ x,      const float* __restrict__ hidden,
        const float* __restrict__ W_in,   const float* __restrict__ b_in,
        const float* __restrict__ cell_W, const float* __restrict__ cell_b,
        const float* __restrict__ upd_W,  const float* __restrict__ upd_b,
        const float* __restrict__ rst_W,  const float* __restrict__ rst_b,
        const float* __restrict__ tau,
        const float* __restrict__ lc_W,   const float* __restrict__ lc_b,
        const float* __restrict__ sk_W,   const float* __restrict__ sk_b,
        const float* __restrict__ fb_W,   const float* __restrict__ fb_b,
        const float* __restrict__ ln_w,   const float* __restrict__ ln_b,
        const float* __restrict__ mn_w,   const float* __restrict__ mn_b,
        float* __restrict__ out)
{
    extern __shared__ float dyn[];
    float* sA = dyn;
    float* sB = dyn + 2 * SA_BUF;
    __shared__ float sMu[NB], sRi[NB];
    __shared__ float sR1[NTHR], sR2[NTHR];
    __shared__ float sW1[16], sW2[16];

    const int tid = threadIdx.x;
    const int bid = blockIdx.x;
    unsigned sense;
    asm volatile("ld.global.acquire.gpu.u32 %0, [%1];" : "=r"(sense) : "l"(&g_sense) : "memory");

    const int arow = tid >> 3, akq = tid & 7;
    int bcol[4], bkq[4];
#pragma unroll
    for (int i = 0; i < 4; i++) { int id = tid + i * NTHR; bcol[i] = id >> 3; bkq[i] = id & 7; }
    const int r0 = (tid >> 6) * 8;
    const int c0 = (tid & 63) * 4;

    // ---- init: h copy, precompute cWc/cbc/dcoef, input projection ----
    for (int i = bid * NTHR + tid; i < 2 * NB * NM; i += NBLK * NTHR)
        g_h[i] = hidden[i];
    for (size_t i = (size_t)bid * NTHR + tid; i < (size_t)NH * NM; i += (size_t)NBLK * NTHR)
        g_cWc[i] = sk_W[i] + lc_W[i];
    for (int i = bid * NTHR + tid; i < NH; i += NBLK * NTHR)
        g_cbc[i] = sk_b[i] + lc_b[i];
    for (int i = bid * NTHR + tid; i < 2 * NM; i += NBLK * NTHR) {
        float tv = tau[i];
        float sp = (tv > 20.f) ? tv : log1pf(expf(tv));
        float tc = fminf(fmaxf(sp, 0.1f), 10.f);
        g_dcoef[i] = expf(-1.f / tc);
    }

    // input projection: xp = x . W_in^T  (2048 tasks of 64x256, dbuf pipeline)
    for (int p = 0; p < 16; p++) {
        int task = bid + p * NBLK;
        int rowBase = (task >> 3) * 64, colBase = (task & 7) * 256;
        ull acc[4][4];
#pragma unroll
        for (int i = 0; i < 4; i++)
#pragma unroll
            for (int j = 0; j < 4; j++) acc[i][j] = 0ull;
        float4 ra, rb[4];
        ra = *(const float4*)(x + (size_t)(rowBase + arow) * NIN + akq * 4);
#pragma unroll
        for (int i = 0; i < 4; i++)
            rb[i] = *(const float4*)(W_in + (size_t)(colBase + bcol[i]) * NIN + bkq[i] * 4);
        STORE_AB(0);
        __syncthreads();
        for (int ku = 0; ku < 32; ku++) {
            if (ku + 1 < 32) {
                int kc = (ku + 1) * 32;
                ra = *(const float4*)(x + (size_t)(rowBase + arow) * NIN + kc + akq * 4);
#pragma unroll
                for (int i = 0; i < 4; i++)
                    rb[i] = *(const float4*)(W_in + (size_t)(colBase + bcol[i]) * NIN + kc + bkq[i] * 4);
            }
            mm_k32(acc, sA + (ku & 1) * SA_BUF, sB + (ku & 1) * SB_BUF, r0, c0);
            if (ku + 1 < 32) STORE_AB((ku + 1) & 1);
            __syncthreads();
        }
#pragma unroll
        for (int rp = 0; rp < 4; rp++) {
            float2 p0 = unp(acc[rp][0]), p1 = unp(acc[rp][1]);
            float2 p2 = unp(acc[rp][2]), p3 = unp(acc[rp][3]);
            float4 lo = {p0.x, p1.x, p2.x, p3.x};
            float4 hi = {p0.y, p1.y, p2.y, p3.y};
            size_t rr = (size_t)rowBase + r0 + 2 * rp;
            *(float4*)(g_xp + rr * NH + colBase + c0) = lo;
            *(float4*)(g_xp + (rr + 1) * NH + colBase + c0) = hi;
        }
    }
    gbar(sense);

    // ---- time loop ----
    for (int t = 0; t < NT; t++) {
        for (int l = 0; l < 2; l++) {
            const float* hsrc = (l == 0) ? (g_h + NB * NM) : g_h;

            // ======== phase P: slab GEMM 8 coltiles x 16 K-splits ========
            {
                const int coltile = bid >> 4, split = bid & 15;
                const int kb = split * 32, colBase = coltile * 256;
                const float* Wb = (l == 0) ? fb_W : g_cWc;
                ull acc[4][4];
#pragma unroll
                for (int i = 0; i < 4; i++)
#pragma unroll
                    for (int j = 0; j < 4; j++) acc[i][j] = 0ull;
                float4 ra, rb[4];
                ra = *(const float4*)(hsrc + (size_t)arow * NM + kb + akq * 4);
#pragma unroll
                for (int i = 0; i < 4; i++)
                    rb[i] = *(const float4*)(Wb + (size_t)(colBase + bcol[i]) * NM + kb + bkq[i] * 4);
                STORE_AB(0);
                __syncthreads();
                mm_k32(acc, sA, sB, r0, c0);
#pragma unroll
                for (int rp = 0; rp < 4; rp++) {
                    float2 p0 = unp(acc[rp][0]), p1 = unp(acc[rp][1]);
                    float2 p2 = unp(acc[rp][2]), p3 = unp(acc[rp][3]);
                    float4 lo = {p0.x, p1.x, p2.x, p3.x};
                    float4 hi = {p0.y, p1.y, p2.y, p3.y};
                    int row = r0 + 2 * rp;
                    *(float4*)(g_pp + ((size_t)split * NB + row) * NH + colBase + c0) = lo;
                    *(float4*)(g_pp + ((size_t)split * NB + row + 1) * NH + colBase + c0) = hi;
                }
            }
            gbar(sense);

            // ======== phase R: reduce P splits + biases + linraw + stat partials ====
            {
                const int row = bid >> 1, half = bid & 1;
                const int c = half * 1024 + tid * 2;
                float2 acc2 = {0.f, 0.f};
#pragma unroll
                for (int s = 0; s < 16; s++) {
                    float2 v = *(const float2*)(g_pp + ((size_t)s * NB + row) * NH + c);
                    acc2.x += v.x; acc2.y += v.y;
                }
                float2 val;
                if (l == 0) {
                    float fbscale = (t == 0) ? 0.f : 0.1f;
                    float2 xv = *(const float2*)(g_xp + ((size_t)row * NT + t) * NH + c);
                    float2 bi = *(const float2*)(b_in + c);
                    float2 fbb = *(const float2*)(fb_b + c);
                    val.x = xv.x + bi.x + fbscale * (acc2.x + fbb.x);
                    val.y = xv.y + bi.y + fbscale * (acc2.y + fbb.y);
                } else {
                    float2 cb = *(const float2*)(g_cbc + c);
                    val.x = acc2.x + cb.x;
                    val.y = acc2.y + cb.y;
                }
                *(float2*)(g_linraw + (size_t)row * NH + c) = val;
                float s1 = val.x + val.y;
                float s2 = val.x * val.x + val.y * val.y;
#pragma unroll
                for (int off = 16; off > 0; off >>= 1) {
                    s1 += __shfl_xor_sync(0xffffffffu, s1, off);
                    s2 += __shfl_xor_sync(0xffffffffu, s2, off);
                }
                if ((tid & 31) == 0) { sW1[tid >> 5] = s1; sW2[tid >> 5] = s2; }
                __syncthreads();
                if (tid == 0) {
                    float t1 = 0.f, t2 = 0.f;
#pragma unroll
                    for (int w = 0; w < 16; w++) { t1 += sW1[w]; t2 += sW2[w]; }
                    g_ps1[bid] = t1;
                    g_ps2[bid] = t2;
                }
            }
            gbar(sense);

            // ======== phase G: stacked-gate GEMM, LN fused in A-load ========
            {
                if (tid < NB) {
                    float s1 = g_ps1[2 * tid] + g_ps1[2 * tid + 1];
                    float s2 = g_ps2[2 * tid] + g_ps2[2 * tid + 1];
                    float mu = s1 * (1.f / NH);
                    sMu[tid] = mu;
                    sRi[tid] = rsqrtf(s2 * (1.f / NH) - mu * mu + 1e-5f);
                }
                __syncthreads();
                int split, nk, kb, outCol, ldb;
                const float* Wb;
                if (bid < 96) {
                    int coltile = bid / 24; split = bid % 24;
                    nk = (split < 8) ? 4 : 3;
                    kb = ((split < 8) ? 4 * split : 32 + 3 * (split - 8)) * 32;
                    int colBase = coltile * 256;
                    if (colBase < 512) Wb = upd_W + ((size_t)l * NM + colBase) * NHM;
                    else               Wb = rst_W + ((size_t)l * NM + colBase - 512) * NHM;
                    ldb = NHM; outCol = colBase;
                } else {
                    int b2 = bid - 96;
                    int coltile = b2 >> 4; split = b2 & 15;
                    nk = 4; kb = split * 128;
                    int colBase = coltile * 256;
                    Wb = cell_W + ((size_t)l * NM + colBase) * NH;
                    ldb = NH; outCol = 1024 + colBase;
                }
                const float* hself = g_h + l * NB * NM;
                const float* lnwl = ln_w + l * NH;
                const float* lnbl = ln_b + l * NH;
                ull acc[4][4];
#pragma unroll
                for (int i = 0; i < 4; i++)
#pragma unroll
                    for (int j = 0; j < 4; j++) acc[i][j] = 0ull;
                float4 ra, rb[4];
#define G_LOAD(KU) do { \
    int kc = kb + (KU) * 32; \
    int kg = kc + akq * 4; \
    if (kg < NH) { \
        ra = *(const float4*)(g_linraw + (size_t)arow * NH + kg); \
        float4 w = *(const float4*)(lnwl + kg); \
        float4 b2v = *(const float4*)(lnbl + kg); \
        float mu = sMu[arow], ri = sRi[arow]; \
        ra.x = (ra.x - mu) * ri * w.x + b2v.x; \
        ra.y = (ra.y - mu) * ri * w.y + b2v.y; \
        ra.z = (ra.z - mu) * ri * w.z + b2v.z; \
        ra.w = (ra.w - mu) * ri * w.w + b2v.w; \
    } else { \
        ra = *(const float4*)(hself + (size_t)arow * NM + (kg - NH)); \
    } \
    _Pragma("unroll") \
    for (int i2 = 0; i2 < 4; i2++) \
        rb[i2] = *(const float4*)(Wb + (size_t)bcol[i2] * ldb + kc + bkq[i2] * 4); \
} while (0)
                G_LOAD(0);
                STORE_AB(0);
                __syncthreads();
                for (int ku = 0; ku < nk; ku++) {
                    if (ku + 1 < nk) G_LOAD(ku + 1);
                    mm_k32(acc, sA + (ku & 1) * SA_BUF, sB + (ku & 1) * SB_BUF, r0, c0);
                    if (ku + 1 < nk) STORE_AB((ku + 1) & 1);
                    __syncthreads();
                }
#pragma unroll
                for (int rp = 0; rp < 4; rp++) {
                    float2 p0 = unp(acc[rp][0]), p1 = unp(acc[rp][1]);
                    float2 p2 = unp(acc[rp][2]), p3 = unp(acc[rp][3]);
                    float4 lo = {p0.x, p1.x, p2.x, p3.x};
                    float4 hi = {p0.y, p1.y, p2.y, p3.y};
                    int row = r0 + 2 * rp;
                    *(float4*)(g_gp + ((size_t)split * NB + row) * NG + outCol + c0) = lo;
                    *(float4*)(g_gp + ((size_t)split * NB + row + 1) * NG + outCol + c0) = hi;
                }
            }
            gbar(sense);

            // ======== phase C: split reduce + gates + mem-LN + write ========
            if (bid < NB) {
                int b = bid, m = tid;
                float* hl = g_h + l * NB * NM;
                float su = 0.f, sr = 0.f, sc = 0.f;
#pragma unroll
                for (int s = 0; s < 24; s++) {
                    size_t base = ((size_t)s * NB + b) * NG;
                    su += g_gp[base + m];
                    sr += g_gp[base + 512 + m];
                }
#pragma unroll
                for (int s = 0; s < 16; s++)
                    sc += g_gp[((size_t)s * NB + b) * NG + 1024 + m];
                int lm = l * NM + m;
                float u = 1.f / (1.f + expf(-(su + upd_b[lm])));
                float r = 1.f / (1.f + expf(-(sr + rst_b[lm])));
                float cand = tanhf(sc + cell_b[lm]);
                float d = g_dcoef[lm] * u;
                float hp = hl[(size_t)b * NM + m];
                float hn = d * (hp * r) + (1.f - d) * cand;
                sR1[tid] = hn;
                sR2[tid] = hn * hn;
                __syncthreads();
                for (int s = NTHR / 2; s > 0; s >>= 1) {
                    if (tid < s) { sR1[tid] += sR1[tid + s]; sR2[tid] += sR2[tid + s]; }
                    __syncthreads();
                }
                float mu = sR1[0] * (1.f / NM);
                float ri = rsqrtf(sR2[0] * (1.f / NM) - mu * mu + 1e-5f);
                float v = (hn - mu) * ri * mn_w[lm] + mn_b[lm];
                hl[(size_t)b * NM + m] = v;
                if (l == 1) out[((size_t)b * NT + t) * NM + m] = v;
            }
            gbar(sense);
        }
    }

    // ---- final hidden states hT appended after outs [B,T,M] ----
    for (int i = bid * NTHR + tid; i < 2 * NB * NM; i += NBLK * NTHR)
        out[(size_t)NB * NT * NM + i] = g_h[i];
}

extern "C" void kernel_launch(void* const* d_in, const int* in_sizes, int n_in,
                              void* d_out, int out_size)
{
    const float* x      = (const float*)d_in[0];
    const float* hidden = (const float*)d_in[1];
    const float* W_in   = (const float*)d_in[2];
    const float* b_in   = (const float*)d_in[3];
    const float* cell_W = (const float*)d_in[4];
    const float* cell_b = (const float*)d_in[5];
    const float* upd_W  = (const float*)d_in[6];
    const float* upd_b  = (const float*)d_in[7];
    const float* rst_W  = (const float*)d_in[8];
    const float* rst_b  = (const float*)d_in[9];
    const float* tau    = (const float*)d_in[10];
    const float* lc_W   = (const float*)d_in[11];
    const float* lc_b   = (const float*)d_in[12];
    const float* sk_W   = (const float*)d_in[13];
    const float* sk_b   = (const float*)d_in[14];
    const float* fb_W   = (const float*)d_in[15];
    const float* fb_b   = (const float*)d_in[16];
    const float* ln_w   = (const float*)d_in[17];
    const float* ln_b   = (const float*)d_in[18];
    const float* mn_w   = (const float*)d_in[19];
    const float* mn_b   = (const float*)d_in[20];
    float* out = (float*)d_out;

    cudaFuncSetAttribute(ltc_all, cudaFuncAttributeMaxDynamicSharedMemorySize, DYN_BYTES);
    ltc_all<<<NBLK, NTHR, DYN_BYTES>>>(x, hidden, W_in, b_in, cell_W, cell_b,
                                       upd_W, upd_b, rst_W, rst_b, tau,
                                       lc_W, lc_b, sk_W, sk_b, fb_W, fb_b,
                                       ln_w, ln_b, mn_w, mn_b, out);
}